// round 15
// baseline (speedup 1.0000x reference)
#include <cuda_runtime.h>
#include <cuda_bf16.h>
#include <cuda_fp16.h>
#include <math.h>
#include <stdint.h>

#define NS   16
#define LL   256
#define HH   128
#define LAMF 20.0f
#define EPSF 1e-8f
#define NARC (NS * LL * LL)
#define NCHUNK 8192
#define MLP_GRID2 296
#define NITEMS (NCHUNK + 576)   // 16 * (512 + 36) = 8768

// -------- scratch --------
__device__ __align__(16) float g_C [NARC];
__device__ unsigned int g_maxabs[NS];
__device__ __align__(16) __nv_bfloat16 g_Kph [NARC];
__device__ __align__(16) __nv_bfloat16 g_KMph[NARC];

// ================= PTX helpers (baseline sm_103) =================
__device__ __forceinline__ uint32_t smem_u32(const void* p) {
    uint32_t a;
    asm("{ .reg .u64 t; cvta.to.shared.u64 t, %1; cvt.u32.u64 %0, t; }" : "=r"(a) : "l"(p));
    return a;
}
#define LDSM_X4T(r, addr) \
    asm volatile("ldmatrix.sync.aligned.m8n8.x4.trans.shared.b16 {%0,%1,%2,%3}, [%4];" \
        : "=r"((r)[0]), "=r"((r)[1]), "=r"((r)[2]), "=r"((r)[3]) : "r"(addr))
#define MMA_BF16(d, a, b) \
    asm volatile("mma.sync.aligned.m16n8k16.row.col.f32.bf16.bf16.f32 " \
        "{%0,%1,%2,%3}, {%4,%5,%6,%7}, {%8,%9}, {%0,%1,%2,%3};" \
        : "+f"((d)[0]), "+f"((d)[1]), "+f"((d)[2]), "+f"((d)[3]) \
        : "r"((a)[0]), "r"((a)[1]), "r"((a)[2]), "r"((a)[3]), "r"((b)[0]), "r"((b)[1]))
#define MMA_F16(d, a, b) \
    asm volatile("mma.sync.aligned.m16n8k16.row.col.f32.f16.f16.f32 " \
        "{%0,%1,%2,%3}, {%4,%5,%6,%7}, {%8,%9}, {%0,%1,%2,%3};" \
        : "+f"((d)[0]), "+f"((d)[1]), "+f"((d)[2]), "+f"((d)[3]) \
        : "r"((a)[0]), "r"((a)[1]), "r"((a)[2]), "r"((a)[3]), "r"((b)[0]), "r"((b)[1]))
__device__ __forceinline__ void sts32(uint32_t addr, uint32_t v) {
    asm volatile("st.shared.b32 [%0], %1;" :: "r"(addr), "r"(v) : "memory");
}
__device__ __forceinline__ float lds32f(uint32_t addr) {
    float v; asm volatile("ld.shared.f32 %0, [%1];" : "=f"(v) : "r"(addr)); return v;
}
__device__ __forceinline__ void sts32f(uint32_t addr, float v) {
    asm volatile("st.shared.f32 [%0], %1;" :: "r"(addr), "f"(v) : "memory");
}
#define CVT2BF(dst, hi, lo) \
    asm("cvt.rn.bf16x2.f32 %0, %1, %2;" : "=r"(dst) : "f"(hi), "f"(lo))
__device__ __forceinline__ uint32_t pack_bf16(__nv_bfloat16 a, __nv_bfloat16 b) {
    __nv_bfloat162 p = __halves2bfloat162(a, b);
    return *reinterpret_cast<uint32_t*>(&p);
}
__device__ __forceinline__ uint32_t pack_h16f(float a, float b) {
    uint32_t r;
    asm("cvt.rn.f16x2.f32 %0, %1, %2;" : "=r"(r) : "f"(b), "f"(a));
    return r;
}
__device__ __forceinline__ float ftanh(float x) {
    float r; asm("tanh.approx.f32 %0, %1;" : "=f"(r) : "f"(x)); return r;
}

// -------- init --------
__global__ void init_kernel(float* __restrict__ loss) {
    int idx = threadIdx.x;
    if (idx < NS) g_maxabs[idx] = 0u;
    if (idx == 0) *loss = 0.0f;
}

// ============ MERGED: block-aligned schedule for L2 reuse ============
// per sample: for b in 0..7: [64 MLP chunks of row-block b] then [b+1 cost tiles (bi<=b, bj=b)]
#define PITCHB 272

__global__ void __launch_bounds__(256, 2) merged_kernel(
    const float* __restrict__ f,  const float* __restrict__ W1,
    const float* __restrict__ b1, const float* __restrict__ W2,
    const float* __restrict__ b2, float* __restrict__ scores)
{
    const int tid = threadIdx.x;
    const int w = tid >> 5, lane = tid & 31;

    __shared__ __align__(16) __half Wh[8 * 16 * 136];
    __shared__ float b1s[128], w2s[128];

    for (int i = tid; i < 16384; i += 256) {
        int k = i >> 7, nn = i & 127;
        Wh[k * 136 + nn] = __float2half_rn(W1[i]);
    }
    if (tid < 128) { b1s[tid] = b1[tid]; w2s[tid] = W2[tid]; }
    __syncthreads();

    const float b2v = __ldg(b2);
    const int g = lane >> 2, t = lane & 3;
    const int lr = lane & 15, lh = lane >> 4;
    const uint32_t wb = smem_u32(Wh);
    const uint32_t b_off = wb + (uint32_t)(lr * PITCHB + lh * 16);

    for (int s = blockIdx.x; s < NITEMS; s += MLP_GRID2) {
        // ---- decode slot: sample n, row-block b, chunk-or-tile ----
        const int n = s / 548;
        int r = s - n * 548;
        int b = 0;
        while (r >= 64 + b + 1) { r -= 64 + b + 1; b++; }
        if (r >= 64) {
            // ---------- COST TILE (bi = r-64, bj = b), whole CTA ----------
            const int bi = r - 64, bj = b;
            const float* fn = f + (size_t)n * (LL * LL * HH);
            float* C = g_C + (size_t)n * (LL * LL);
            float lmax = 0.0f;
#pragma unroll 1
            for (int a0 = w * 4; a0 < 1024; a0 += 32) {
                int rr = a0 >> 5, cc = a0 & 31;
                int i = bi * 32 + rr;
                float4 x[4], y[4];
#pragma unroll
                for (int p = 0; p < 4; p++) {
                    int j = bj * 32 + cc + p;
                    if (j >= i) {
                        x[p] = __ldg((const float4*)(fn + (size_t)(i * LL + j) * HH) + lane);
                        y[p] = __ldg((const float4*)(fn + (size_t)(j * LL + i) * HH) + lane);
                    } else {
                        x[p] = make_float4(0.f, 0.f, 0.f, 0.f);
                        y[p] = x[p];
                    }
                }
                float sv[4];
#pragma unroll
                for (int p = 0; p < 4; p++)
                    sv[p] = x[p].x * y[p].x + x[p].y * y[p].y + x[p].z * y[p].z + x[p].w * y[p].w;
#pragma unroll
                for (int o = 16; o > 0; o >>= 1) {
#pragma unroll
                    for (int p = 0; p < 4; p++) sv[p] += __shfl_xor_sync(0xffffffffu, sv[p], o);
                }
                if (lane == 0) {
#pragma unroll
                    for (int p = 0; p < 4; p++) {
                        int j = bj * 32 + cc + p;
                        if (j >= i) {
                            C[i * LL + j] = sv[p];
                            C[j * LL + i] = sv[p];
                            lmax = fmaxf(lmax, fabsf(sv[p]));
                        }
                    }
                }
            }
            if (lane == 0) atomicMax(&g_maxabs[n], __float_as_uint(lmax));
            continue;
        }
        // ---------- MLP CHUNK ----------
        const int chunk = n * 512 + b * 64 + r;
        const float* fb = f + (size_t)chunk * 16384 + (size_t)(w * 16 + g) * 128 + 2 * t;
        float2 af[8][4];
#pragma unroll
        for (int ks = 0; ks < 8; ks++) {
            af[ks][0] = __ldg((const float2*)(fb + ks * 16));
            af[ks][1] = __ldg((const float2*)(fb + ks * 16 + 8 * 128));
            af[ks][2] = __ldg((const float2*)(fb + ks * 16 + 8));
            af[ks][3] = __ldg((const float2*)(fb + ks * 16 + 8 * 128 + 8));
        }
        uint32_t ah[8][4];
#pragma unroll
        for (int ks = 0; ks < 8; ks++)
#pragma unroll
            for (int q = 0; q < 4; q++)
                ah[ks][q] = pack_h16f(af[ks][q].x, af[ks][q].y);

        float D[16][4];
#pragma unroll
        for (int nf = 0; nf < 16; nf++)
#pragma unroll
            for (int q = 0; q < 4; q++) D[nf][q] = 0.0f;

#pragma unroll
        for (int ks = 0; ks < 8; ks++) {
            uint32_t bh[16][2];
#pragma unroll
            for (int p = 0; p < 8; p++) {
                uint32_t rr[4];
                LDSM_X4T(rr, b_off + ks * (16 * PITCHB) + p * 32);
                bh[2*p][0] = rr[0]; bh[2*p][1] = rr[1];
                bh[2*p+1][0] = rr[2]; bh[2*p+1][1] = rr[3];
            }
#pragma unroll
            for (int nf = 0; nf < 16; nf++)
                MMA_F16(D[nf], ah[ks], bh[nf]);
        }

        float plo = 0.0f, phi = 0.0f;
#pragma unroll
        for (int nf = 0; nf < 16; nf++) {
            int col = nf * 8 + 2 * t;
            float b1a = b1s[col], b1b = b1s[col + 1];
            float w2a = w2s[col], w2b = w2s[col + 1];
            plo += ftanh(D[nf][0] + b1a) * w2a + ftanh(D[nf][1] + b1b) * w2b;
            phi += ftanh(D[nf][2] + b1a) * w2a + ftanh(D[nf][3] + b1b) * w2b;
        }
        plo += __shfl_xor_sync(0xffffffffu, plo, 1);
        plo += __shfl_xor_sync(0xffffffffu, plo, 2);
        phi += __shfl_xor_sync(0xffffffffu, phi, 1);
        phi += __shfl_xor_sync(0xffffffffu, phi, 2);
        if (t == 0) {
            float* so = scores + (size_t)chunk * 128 + w * 16 + g;
            so[0] = plo + b2v;
            so[8] = phi + b2v;
        }
    }
}

// -------- kexp: gather-8, one 16B store per array --------
__global__ void __launch_bounds__(256) kexp_kernel() {
    int gid = blockIdx.x * 256 + threadIdx.x;        // 131072 groups
    int n = gid >> 13;
    int g2 = gid & 8191;
    int tilepair = g2 >> 5, T = g2 & 31;
    int mt = tilepair >> 4, kt = tilepair & 15;
    int r0 = mt * 16 + (T >> 2);
    int k0 = kt * 16 + 2 * (T & 3);
    const float* C = g_C + ((size_t)n << 16);
    float mx = __uint_as_float(g_maxabs[n]);
    float inv = __fdividef(1.0f, mx + EPSF);

    float2 c00 = *(const float2*)(C + r0 * 256 + k0);
    float2 c10 = *(const float2*)(C + (r0 + 8) * 256 + k0);
    float2 c01 = *(const float2*)(C + r0 * 256 + k0 + 8);
    float2 c11 = *(const float2*)(C + (r0 + 8) * 256 + k0 + 8);
    float cv[8] = { c00.x, c00.y, c10.x, c10.y, c01.x, c01.y, c11.x, c11.y };

    uint32_t kh[4], mh[4];
#pragma unroll
    for (int p = 0; p < 4; p++) {
        float cn0 = cv[2*p]     * inv;
        float cn1 = cv[2*p + 1] * inv;
        float kv0 = __expf(-LAMF * cn0);
        float kv1 = __expf(-LAMF * cn1);
        CVT2BF(kh[p], kv1, kv0);
        CVT2BF(mh[p], kv1 * cn1, kv0 * cn0);
    }
    ((uint4*)g_Kph )[gid] = make_uint4(kh[0], kh[1], kh[2], kh[3]);
    ((uint4*)g_KMph)[gid] = make_uint4(mh[0], mh[1], mh[2], mh[3]);
}

// ============ fused Sinkhorn: 1-term K iters + 1-term KM loss, dbl-buffered X ============
#define SK_X0  0
#define SK_X1  20480
#define SK_UN  40960
#define SK_CN  74752
#define SK_UF  108544
#define SK_RED 142336
#define SK_SMEM 142400

template<bool STORE_U>
__device__ __noinline__ void sink_phase(
    const uint4* __restrict__ Ah,
    uint32_t xr, uint32_t xw, uint32_t nmb, uint32_t ufb, int w, int lane)
{
    float D[4][4];
#pragma unroll
    for (int j = 0; j < 4; j++)
#pragma unroll
        for (int q = 0; q < 4; q++) D[j][q] = 0.0f;

    const int lr = lane & 15, lh = lane >> 4;
    const uint32_t bhb = xr + lr * 80 + lh * 16;
#pragma unroll 4
    for (int kt = 0; kt < 16; kt++) {
        uint4 ah = Ah[(size_t)(w * 16 + kt) * 32 + lane];
        uint32_t bh[4][2], r[4];
        LDSM_X4T(r, bhb + kt * 1280);      bh[0][0]=r[0]; bh[0][1]=r[1]; bh[1][0]=r[2]; bh[1][1]=r[3];
        LDSM_X4T(r, bhb + kt * 1280 + 32); bh[2][0]=r[0]; bh[2][1]=r[1]; bh[3][0]=r[2]; bh[3][1]=r[3];
#pragma unroll
        for (int nt = 0; nt < 4; nt++)
            MMA_BF16(D[nt], ((uint32_t*)&ah), bh[nt]);
    }
    const int rq = lane >> 2, cq = (lane & 3) * 2;
    const int row = w * 16 + rq;
#pragma unroll
    for (int nt = 0; nt < 4; nt++) {
        int col = nt * 8 + cq;
        float n0 = lds32f(nmb + (row * 33 + col) * 4);
        float n1 = lds32f(nmb + (row * 33 + col + 1) * 4);
        float n2 = lds32f(nmb + ((row + 8) * 33 + col) * 4);
        float n3 = lds32f(nmb + ((row + 8) * 33 + col + 1) * 4);
        float o0 = __fdividef(n0, D[nt][0] + EPSF);
        float o1 = __fdividef(n1, D[nt][1] + EPSF);
        float o2 = __fdividef(n2, D[nt][2] + EPSF);
        float o3 = __fdividef(n3, D[nt][3] + EPSF);
        uint32_t h01, h23;
        CVT2BF(h01, o1, o0);
        CVT2BF(h23, o3, o2);
        sts32(xw + row * 80 + col * 2, h01);
        sts32(xw + (row + 8) * 80 + col * 2, h23);
        if (STORE_U) {
            sts32f(ufb + (row * 33 + col) * 4, o0);
            sts32f(ufb + (row * 33 + col + 1) * 4, o1);
            sts32f(ufb + ((row + 8) * 33 + col) * 4, o2);
            sts32f(ufb + ((row + 8) * 33 + col + 1) * 4, o3);
        }
    }
    __syncthreads();
}

__global__ void __launch_bounds__(512, 1) sinkhorn_fused_kernel(
    const float* __restrict__ scores, const float* __restrict__ head,
    float* __restrict__ loss)
{
    extern __shared__ __align__(16) char smem[];
    const uint32_t sb = smem_u32(smem);
    const int tid = threadIdx.x, lane = tid & 31, w = tid >> 5;
    const int n = blockIdx.x >> 3, c0 = (blockIdx.x & 7) * 32;

    float* UN = (float*)(smem + SK_UN);
    float* CN = (float*)(smem + SK_CN);
#pragma unroll
    for (int q = 0; q < 2; q++) {
        int p = w * 2 + q;
        const float* row = scores + ((size_t)(n * 256 + c0 + p)) * 256;
        float4 v0 = *(const float4*)(row + lane * 4);
        float4 v1 = *(const float4*)(row + 128 + lane * 4);
        float m = fmaxf(fmaxf(fmaxf(v0.x, v0.y), fmaxf(v0.z, v0.w)),
                        fmaxf(fmaxf(v1.x, v1.y), fmaxf(v1.z, v1.w)));
#pragma unroll
        for (int o = 16; o > 0; o >>= 1) m = fmaxf(m, __shfl_xor_sync(0xffffffffu, m, o));
        float e[8];
        e[0] = __expf(v0.x - m); e[1] = __expf(v0.y - m);
        e[2] = __expf(v0.z - m); e[3] = __expf(v0.w - m);
        e[4] = __expf(v1.x - m); e[5] = __expf(v1.y - m);
        e[6] = __expf(v1.z - m); e[7] = __expf(v1.w - m);
        float sum = e[0]+e[1]+e[2]+e[3]+e[4]+e[5]+e[6]+e[7];
#pragma unroll
        for (int o = 16; o > 0; o >>= 1) sum += __shfl_xor_sync(0xffffffffu, sum, o);
        float inv = __fdividef(1.0f, sum);
#pragma unroll
        for (int k = 0; k < 4; k++) UN[(lane * 4 + k) * 33 + p]       = e[k] * inv;
#pragma unroll
        for (int k = 0; k < 4; k++) UN[(128 + lane * 4 + k) * 33 + p] = e[4 + k] * inv;

        const float* hrow = head + ((size_t)(n * 256 + c0 + p)) * 256;
        float4 h0 = *(const float4*)(hrow + lane * 4);
        float4 h1 = *(const float4*)(hrow + 128 + lane * 4);
        float he[8] = { h0.x + EPSF, h0.y + EPSF, h0.z + EPSF, h0.w + EPSF,
                        h1.x + EPSF, h1.y + EPSF, h1.z + EPSF, h1.w + EPSF };
        float hsum = he[0]+he[1]+he[2]+he[3]+he[4]+he[5]+he[6]+he[7];
#pragma unroll
        for (int o = 16; o > 0; o >>= 1) hsum += __shfl_xor_sync(0xffffffffu, hsum, o);
        float hinv = __fdividef(1.0f, hsum);
#pragma unroll
        for (int k = 0; k < 4; k++) CN[(lane * 4 + k) * 33 + p]       = he[k] * hinv;
#pragma unroll
        for (int k = 0; k < 4; k++) CN[(128 + lane * 4 + k) * 33 + p] = he[4 + k] * hinv;
    }
    const uint32_t HV = pack_bf16(__float2bfloat16(1.0f / 256.0f),
                                  __float2bfloat16(1.0f / 256.0f));
    for (int i = tid; i < 5120; i += 512)
        ((uint32_t*)(smem + SK_X0))[i] = HV;
    __syncthreads();

    const uint4* Kh  = (const uint4*)g_Kph  + (size_t)n * 8192;
    const uint4* Mh  = (const uint4*)g_KMph + (size_t)n * 8192;
    const uint32_t xA = sb + SK_X0, xB = sb + SK_X1;
    const uint32_t unb = sb + SK_UN, cnb = sb + SK_CN, ufb = sb + SK_UF;

#pragma unroll 1
    for (int it = 0; it < 19; it++) {
        sink_phase<false>(Kh, xA, xB, cnb, ufb, w, lane);
        sink_phase<false>(Kh, xB, xA, unb, ufb, w, lane);
    }
    sink_phase<false>(Kh, xA, xB, cnb, ufb, w, lane);
    sink_phase<true >(Kh, xB, xA, unb, ufb, w, lane);   // u -> ufb
    sink_phase<false>(Kh, xA, xB, cnb, ufb, w, lane);   // v -> xB

    // loss partial: sum u .* (KM @ v)
    float D[4][4];
#pragma unroll
    for (int j = 0; j < 4; j++)
#pragma unroll
        for (int q = 0; q < 4; q++) D[j][q] = 0.0f;
    {
        const int lr = lane & 15, lh = lane >> 4;
        const uint32_t bhb = xB + lr * 80 + lh * 16;
#pragma unroll 4
        for (int kt = 0; kt < 16; kt++) {
            uint4 ah = Mh[(size_t)(w * 16 + kt) * 32 + lane];
            uint32_t bh[4][2], r[4];
            LDSM_X4T(r, bhb + kt * 1280);      bh[0][0]=r[0]; bh[0][1]=r[1]; bh[1][0]=r[2]; bh[1][1]=r[3];
            LDSM_X4T(r, bhb + kt * 1280 + 32); bh[2][0]=r[0]; bh[2][1]=r[1]; bh[3][0]=r[2]; bh[3][1]=r[3];
#pragma unroll
            for (int nt = 0; nt < 4; nt++)
                MMA_BF16(D[nt], ((uint32_t*)&ah), bh[nt]);
        }
    }
    float part = 0.0f;
    {
        const int rq = lane >> 2, cq = (lane & 3) * 2;
        const int row = w * 16 + rq;
#pragma unroll
        for (int nt = 0; nt < 4; nt++) {
            int col = nt * 8 + cq;
            part += lds32f(ufb + (row * 33 + col) * 4)           * D[nt][0];
            part += lds32f(ufb + (row * 33 + col + 1) * 4)       * D[nt][1];
            part += lds32f(ufb + ((row + 8) * 33 + col) * 4)     * D[nt][2];
            part += lds32f(ufb + ((row + 8) * 33 + col + 1) * 4) * D[nt][3];
        }
    }
#pragma unroll
    for (int o = 16; o > 0; o >>= 1) part += __shfl_xor_sync(0xffffffffu, part, o);
    float* RED = (float*)(smem + SK_RED);
    if (lane == 0) RED[w] = part;
    __syncthreads();
    if (tid == 0) {
        float t = 0.0f;
#pragma unroll
        for (int i = 0; i < 16; i++) t += RED[i];
        atomicAdd(loss, t);
    }
}

extern "C" void kernel_launch(void* const* d_in, const int* in_sizes, int n_in,
                              void* d_out, int out_size)
{
    const float* f    = (const float*)d_in[0];
    const float* head = (const float*)d_in[1];
    const float* W1   = (const float*)d_in[2];
    const float* b1   = (const float*)d_in[3];
    const float* W2   = (const float*)d_in[4];
    const float* b2   = (const float*)d_in[5];
    float* out    = (float*)d_out;
    float* scores = out;
    float* loss   = out + (out_size - 1);

    cudaFuncSetAttribute(sinkhorn_fused_kernel, cudaFuncAttributeMaxDynamicSharedMemorySize, SK_SMEM);

    init_kernel<<<1, 256>>>(loss);
    merged_kernel<<<MLP_GRID2, 256>>>(f, W1, b1, W2, b2, scores);
    kexp_kernel<<<512, 256>>>();
    sinkhorn_fused_kernel<<<128, 512, SK_SMEM>>>(scores, head, loss);
}

// round 16
// speedup vs baseline: 1.1826x; 1.1826x over previous
#include <cuda_runtime.h>
#include <cuda_bf16.h>
#include <cuda_fp16.h>
#include <math.h>
#include <stdint.h>

#define NS   16
#define LL   256
#define HH   128
#define LAMF 20.0f
#define EPSF 1e-8f
#define NARC (NS * LL * LL)
#define NCHUNK 8192
#define MLP_GRID2 296
#define NITEMS (NCHUNK + 576)

// -------- scratch --------
__device__ __align__(16) float g_C [NARC];
__device__ unsigned int g_maxabs[NS];
__device__ __align__(16) __nv_bfloat16 g_Kph [NARC];
__device__ __align__(16) __nv_bfloat16 g_KMph[NARC];

// ================= PTX helpers (baseline sm_103) =================
__device__ __forceinline__ uint32_t smem_u32(const void* p) {
    uint32_t a;
    asm("{ .reg .u64 t; cvta.to.shared.u64 t, %1; cvt.u32.u64 %0, t; }" : "=r"(a) : "l"(p));
    return a;
}
#define LDSM_X4T(r, addr) \
    asm volatile("ldmatrix.sync.aligned.m8n8.x4.trans.shared.b16 {%0,%1,%2,%3}, [%4];" \
        : "=r"((r)[0]), "=r"((r)[1]), "=r"((r)[2]), "=r"((r)[3]) : "r"(addr))
#define MMA_BF16(d, a, b) \
    asm volatile("mma.sync.aligned.m16n8k16.row.col.f32.bf16.bf16.f32 " \
        "{%0,%1,%2,%3}, {%4,%5,%6,%7}, {%8,%9}, {%0,%1,%2,%3};" \
        : "+f"((d)[0]), "+f"((d)[1]), "+f"((d)[2]), "+f"((d)[3]) \
        : "r"((a)[0]), "r"((a)[1]), "r"((a)[2]), "r"((a)[3]), "r"((b)[0]), "r"((b)[1]))
#define MMA_F16(d, a, b) \
    asm volatile("mma.sync.aligned.m16n8k16.row.col.f32.f16.f16.f32 " \
        "{%0,%1,%2,%3}, {%4,%5,%6,%7}, {%8,%9}, {%0,%1,%2,%3};" \
        : "+f"((d)[0]), "+f"((d)[1]), "+f"((d)[2]), "+f"((d)[3]) \
        : "r"((a)[0]), "r"((a)[1]), "r"((a)[2]), "r"((a)[3]), "r"((b)[0]), "r"((b)[1]))
__device__ __forceinline__ void sts32(uint32_t addr, uint32_t v) {
    asm volatile("st.shared.b32 [%0], %1;" :: "r"(addr), "r"(v) : "memory");
}
#define CVT2BF(dst, hi, lo) \
    asm("cvt.rn.bf16x2.f32 %0, %1, %2;" : "=r"(dst) : "f"(hi), "f"(lo))
__device__ __forceinline__ uint32_t pack_bf16(__nv_bfloat16 a, __nv_bfloat16 b) {
    __nv_bfloat162 p = __halves2bfloat162(a, b);
    return *reinterpret_cast<uint32_t*>(&p);
}
__device__ __forceinline__ uint32_t pack_h16f(float a, float b) {
    uint32_t r;
    asm("cvt.rn.f16x2.f32 %0, %1, %2;" : "=r"(r) : "f"(b), "f"(a));
    return r;
}
__device__ __forceinline__ float ftanh(float x) {
    float r; asm("tanh.approx.f32 %0, %1;" : "=f"(r) : "f"(x)); return r;
}

// -------- init --------
__global__ void init_kernel(float* __restrict__ loss) {
    int idx = threadIdx.x;
    if (idx < NS) g_maxabs[idx] = 0u;
    if (idx == 0) *loss = 0.0f;
}

// ============ MERGED (R14 schedule): MLP chunks + uniform-interleaved cost tiles ============
#define PITCHB 272

__global__ void __launch_bounds__(256, 2) merged_kernel(
    const float* __restrict__ f,  const float* __restrict__ W1,
    const float* __restrict__ b1, const float* __restrict__ W2,
    const float* __restrict__ b2, float* __restrict__ scores)
{
    const int tid = threadIdx.x;
    const int w = tid >> 5, lane = tid & 31;

    __shared__ __align__(16) __half Wh[8 * 16 * 136];
    __shared__ float b1s[128], w2s[128];

    for (int i = tid; i < 16384; i += 256) {
        int k = i >> 7, nn = i & 127;
        Wh[k * 136 + nn] = __float2half_rn(W1[i]);
    }
    if (tid < 128) { b1s[tid] = b1[tid]; w2s[tid] = W2[tid]; }
    __syncthreads();

    const float b2v = __ldg(b2);
    const int g = lane >> 2, t = lane & 3;
    const int lr = lane & 15, lh = lane >> 4;
    const uint32_t wb = smem_u32(Wh);
    const uint32_t b_off = wb + (uint32_t)(lr * PITCHB + lh * 16);

    for (int s = blockIdx.x; s < NITEMS; s += MLP_GRID2) {
        const bool is_cost = (s < 8640) && (s % 15 == 14);
        if (is_cost) {
            const int cb = s / 15;
            const int n = cb / 36;
            int tt = cb % 36, bi = 0;
            while (tt >= 8 - bi) { tt -= 8 - bi; bi++; }
            const int bj = bi + tt;
            const float* fn = f + (size_t)n * (LL * LL * HH);
            float* C = g_C + (size_t)n * (LL * LL);
            float lmax = 0.0f;
#pragma unroll 1
            for (int a0 = w * 4; a0 < 1024; a0 += 32) {
                int r = a0 >> 5, cc = a0 & 31;
                int i = bi * 32 + r;
                float4 x[4], y[4];
#pragma unroll
                for (int p = 0; p < 4; p++) {
                    int j = bj * 32 + cc + p;
                    if (j >= i) {
                        x[p] = __ldg((const float4*)(fn + (size_t)(i * LL + j) * HH) + lane);
                        y[p] = __ldg((const float4*)(fn + (size_t)(j * LL + i) * HH) + lane);
                    } else {
                        x[p] = make_float4(0.f, 0.f, 0.f, 0.f);
                        y[p] = x[p];
                    }
                }
                float sv[4];
#pragma unroll
                for (int p = 0; p < 4; p++)
                    sv[p] = x[p].x * y[p].x + x[p].y * y[p].y + x[p].z * y[p].z + x[p].w * y[p].w;
#pragma unroll
                for (int o = 16; o > 0; o >>= 1) {
#pragma unroll
                    for (int p = 0; p < 4; p++) sv[p] += __shfl_xor_sync(0xffffffffu, sv[p], o);
                }
                if (lane == 0) {
#pragma unroll
                    for (int p = 0; p < 4; p++) {
                        int j = bj * 32 + cc + p;
                        if (j >= i) {
                            C[i * LL + j] = sv[p];
                            C[j * LL + i] = sv[p];
                            lmax = fmaxf(lmax, fabsf(sv[p]));
                        }
                    }
                }
            }
            if (lane == 0) atomicMax(&g_maxabs[n], __float_as_uint(lmax));
            continue;
        }
        const int chunk = (s < 8640) ? (s - (s + 1) / 15) : (s - 576);
        const float* fb = f + (size_t)chunk * 16384 + (size_t)(w * 16 + g) * 128 + 2 * t;
        float2 af[8][4];
#pragma unroll
        for (int ks = 0; ks < 8; ks++) {
            af[ks][0] = __ldg((const float2*)(fb + ks * 16));
            af[ks][1] = __ldg((const float2*)(fb + ks * 16 + 8 * 128));
            af[ks][2] = __ldg((const float2*)(fb + ks * 16 + 8));
            af[ks][3] = __ldg((const float2*)(fb + ks * 16 + 8 * 128 + 8));
        }
        uint32_t ah[8][4];
#pragma unroll
        for (int ks = 0; ks < 8; ks++)
#pragma unroll
            for (int q = 0; q < 4; q++)
                ah[ks][q] = pack_h16f(af[ks][q].x, af[ks][q].y);

        float D[16][4];
#pragma unroll
        for (int nf = 0; nf < 16; nf++)
#pragma unroll
            for (int q = 0; q < 4; q++) D[nf][q] = 0.0f;

#pragma unroll
        for (int ks = 0; ks < 8; ks++) {
            uint32_t bh[16][2];
#pragma unroll
            for (int p = 0; p < 8; p++) {
                uint32_t r[4];
                LDSM_X4T(r, b_off + ks * (16 * PITCHB) + p * 32);
                bh[2*p][0] = r[0]; bh[2*p][1] = r[1];
                bh[2*p+1][0] = r[2]; bh[2*p+1][1] = r[3];
            }
#pragma unroll
            for (int nf = 0; nf < 16; nf++)
                MMA_F16(D[nf], ah[ks], bh[nf]);
        }

        float plo = 0.0f, phi = 0.0f;
#pragma unroll
        for (int nf = 0; nf < 16; nf++) {
            int col = nf * 8 + 2 * t;
            float b1a = b1s[col], b1b = b1s[col + 1];
            float w2a = w2s[col], w2b = w2s[col + 1];
            plo += ftanh(D[nf][0] + b1a) * w2a + ftanh(D[nf][1] + b1b) * w2b;
            phi += ftanh(D[nf][2] + b1a) * w2a + ftanh(D[nf][3] + b1b) * w2b;
        }
        plo += __shfl_xor_sync(0xffffffffu, plo, 1);
        plo += __shfl_xor_sync(0xffffffffu, plo, 2);
        phi += __shfl_xor_sync(0xffffffffu, phi, 1);
        phi += __shfl_xor_sync(0xffffffffu, phi, 2);
        if (t == 0) {
            float* so = scores + (size_t)chunk * 128 + w * 16 + g;
            so[0] = plo + b2v;
            so[8] = phi + b2v;
        }
    }
}

// -------- kexp: gather-8, one 16B store per array --------
__global__ void __launch_bounds__(256) kexp_kernel() {
    int gid = blockIdx.x * 256 + threadIdx.x;
    int n = gid >> 13;
    int g2 = gid & 8191;
    int tilepair = g2 >> 5, T = g2 & 31;
    int mt = tilepair >> 4, kt = tilepair & 15;
    int r0 = mt * 16 + (T >> 2);
    int k0 = kt * 16 + 2 * (T & 3);
    const float* C = g_C + ((size_t)n << 16);
    float mx = __uint_as_float(g_maxabs[n]);
    float inv = __fdividef(1.0f, mx + EPSF);

    float2 c00 = *(const float2*)(C + r0 * 256 + k0);
    float2 c10 = *(const float2*)(C + (r0 + 8) * 256 + k0);
    float2 c01 = *(const float2*)(C + r0 * 256 + k0 + 8);
    float2 c11 = *(const float2*)(C + (r0 + 8) * 256 + k0 + 8);
    float cv[8] = { c00.x, c00.y, c10.x, c10.y, c01.x, c01.y, c11.x, c11.y };

    uint32_t kh[4], mh[4];
#pragma unroll
    for (int p = 0; p < 4; p++) {
        float cn0 = cv[2*p]     * inv;
        float cn1 = cv[2*p + 1] * inv;
        float kv0 = __expf(-LAMF * cn0);
        float kv1 = __expf(-LAMF * cn1);
        CVT2BF(kh[p], kv1, kv0);
        CVT2BF(mh[p], kv1 * cn1, kv0 * cn0);
    }
    ((uint4*)g_Kph )[gid] = make_uint4(kh[0], kh[1], kh[2], kh[3]);
    ((uint4*)g_KMph)[gid] = make_uint4(mh[0], mh[1], mh[2], mh[3]);
}

// ============ fused Sinkhorn: register numerators/u, dbl-buffered X ============
#define SK_X0  0
#define SK_X1  20480
#define SK_UN  40960
#define SK_CN  74752
#define SK_RED 108544
#define SK_SMEM 108608

template<bool STORE_U>
__device__ __forceinline__ void sink_phase(
    const uint4* __restrict__ Ah, uint32_t xr, uint32_t xw,
    const float* __restrict__ nm, float* __restrict__ u, int w, int lane)
{
    float D[4][4];
#pragma unroll
    for (int j = 0; j < 4; j++)
#pragma unroll
        for (int q = 0; q < 4; q++) D[j][q] = 0.0f;

    const int lr = lane & 15, lh = lane >> 4;
    const uint32_t bhb = xr + lr * 80 + lh * 16;
#pragma unroll 4
    for (int kt = 0; kt < 16; kt++) {
        uint4 ah = Ah[(size_t)(w * 16 + kt) * 32 + lane];
        uint32_t bh[4][2], r[4];
        LDSM_X4T(r, bhb + kt * 1280);      bh[0][0]=r[0]; bh[0][1]=r[1]; bh[1][0]=r[2]; bh[1][1]=r[3];
        LDSM_X4T(r, bhb + kt * 1280 + 32); bh[2][0]=r[0]; bh[2][1]=r[1]; bh[3][0]=r[2]; bh[3][1]=r[3];
#pragma unroll
        for (int nt = 0; nt < 4; nt++)
            MMA_BF16(D[nt], ((uint32_t*)&ah), bh[nt]);
    }
    const int rq = lane >> 2, cq = (lane & 3) * 2;
    const int row = w * 16 + rq;
#pragma unroll
    for (int nt = 0; nt < 4; nt++) {
        int col = nt * 8 + cq;
        float o0 = __fdividef(nm[nt*4+0], D[nt][0] + EPSF);
        float o1 = __fdividef(nm[nt*4+1], D[nt][1] + EPSF);
        float o2 = __fdividef(nm[nt*4+2], D[nt][2] + EPSF);
        float o3 = __fdividef(nm[nt*4+3], D[nt][3] + EPSF);
        uint32_t h01, h23;
        CVT2BF(h01, o1, o0);
        CVT2BF(h23, o3, o2);
        sts32(xw + row * 80 + col * 2, h01);
        sts32(xw + (row + 8) * 80 + col * 2, h23);
        if (STORE_U) {
            u[nt*4+0] = o0; u[nt*4+1] = o1; u[nt*4+2] = o2; u[nt*4+3] = o3;
        }
    }
    __syncthreads();
}

__global__ void __launch_bounds__(512, 1) sinkhorn_fused_kernel(
    const float* __restrict__ scores, const float* __restrict__ head,
    float* __restrict__ loss)
{
    extern __shared__ __align__(16) char smem[];
    const uint32_t sb = smem_u32(smem);
    const int tid = threadIdx.x, lane = tid & 31, w = tid >> 5;
    const int n = blockIdx.x >> 3, c0 = (blockIdx.x & 7) * 32;

    float* UN = (float*)(smem + SK_UN);
    float* CN = (float*)(smem + SK_CN);
#pragma unroll
    for (int q = 0; q < 2; q++) {
        int p = w * 2 + q;
        const float* row = scores + ((size_t)(n * 256 + c0 + p)) * 256;
        float4 v0 = *(const float4*)(row + lane * 4);
        float4 v1 = *(const float4*)(row + 128 + lane * 4);
        float m = fmaxf(fmaxf(fmaxf(v0.x, v0.y), fmaxf(v0.z, v0.w)),
                        fmaxf(fmaxf(v1.x, v1.y), fmaxf(v1.z, v1.w)));
#pragma unroll
        for (int o = 16; o > 0; o >>= 1) m = fmaxf(m, __shfl_xor_sync(0xffffffffu, m, o));
        float e[8];
        e[0] = __expf(v0.x - m); e[1] = __expf(v0.y - m);
        e[2] = __expf(v0.z - m); e[3] = __expf(v0.w - m);
        e[4] = __expf(v1.x - m); e[5] = __expf(v1.y - m);
        e[6] = __expf(v1.z - m); e[7] = __expf(v1.w - m);
        float sum = e[0]+e[1]+e[2]+e[3]+e[4]+e[5]+e[6]+e[7];
#pragma unroll
        for (int o = 16; o > 0; o >>= 1) sum += __shfl_xor_sync(0xffffffffu, sum, o);
        float inv = __fdividef(1.0f, sum);
#pragma unroll
        for (int k = 0; k < 4; k++) UN[(lane * 4 + k) * 33 + p]       = e[k] * inv;
#pragma unroll
        for (int k = 0; k < 4; k++) UN[(128 + lane * 4 + k) * 33 + p] = e[4 + k] * inv;

        const float* hrow = head + ((size_t)(n * 256 + c0 + p)) * 256;
        float4 h0 = *(const float4*)(hrow + lane * 4);
        float4 h1 = *(const float4*)(hrow + 128 + lane * 4);
        float he[8] = { h0.x + EPSF, h0.y + EPSF, h0.z + EPSF, h0.w + EPSF,
                        h1.x + EPSF, h1.y + EPSF, h1.z + EPSF, h1.w + EPSF };
        float hsum = he[0]+he[1]+he[2]+he[3]+he[4]+he[5]+he[6]+he[7];
#pragma unroll
        for (int o = 16; o > 0; o >>= 1) hsum += __shfl_xor_sync(0xffffffffu, hsum, o);
        float hinv = __fdividef(1.0f, hsum);
#pragma unroll
        for (int k = 0; k < 4; k++) CN[(lane * 4 + k) * 33 + p]       = he[k] * hinv;
#pragma unroll
        for (int k = 0; k < 4; k++) CN[(128 + lane * 4 + k) * 33 + p] = he[4 + k] * hinv;
    }
    const uint32_t HV = pack_bf16(__float2bfloat16(1.0f / 256.0f),
                                  __float2bfloat16(1.0f / 256.0f));
    for (int i = tid; i < 5120; i += 512)
        ((uint32_t*)(smem + SK_X0))[i] = HV;
    __syncthreads();

    // ---- hoist thread-owned numerators into registers ----
    const int rq = lane >> 2, cq = (lane & 3) * 2;
    const int row = w * 16 + rq;
    float un_r[16], cn_r[16], u_r[16];
#pragma unroll
    for (int nt = 0; nt < 4; nt++) {
        int col = nt * 8 + cq;
        un_r[nt*4+0] = UN[row * 33 + col];
        un_r[nt*4+1] = UN[row * 33 + col + 1];
        un_r[nt*4+2] = UN[(row + 8) * 33 + col];
        un_r[nt*4+3] = UN[(row + 8) * 33 + col + 1];
        cn_r[nt*4+0] = CN[row * 33 + col];
        cn_r[nt*4+1] = CN[row * 33 + col + 1];
        cn_r[nt*4+2] = CN[(row + 8) * 33 + col];
        cn_r[nt*4+3] = CN[(row + 8) * 33 + col + 1];
    }

    const uint4* Kh  = (const uint4*)g_Kph  + (size_t)n * 8192;
    const uint4* Mh  = (const uint4*)g_KMph + (size_t)n * 8192;
    const uint32_t xA = sb + SK_X0, xB = sb + SK_X1;

#pragma unroll 1
    for (int it = 0; it < 19; it++) {
        sink_phase<false>(Kh, xA, xB, cn_r, u_r, w, lane);
        sink_phase<false>(Kh, xB, xA, un_r, u_r, w, lane);
    }
    sink_phase<false>(Kh, xA, xB, cn_r, u_r, w, lane);
    sink_phase<true >(Kh, xB, xA, un_r, u_r, w, lane);   // u -> u_r
    sink_phase<false>(Kh, xA, xB, cn_r, u_r, w, lane);   // v -> xB

    // loss partial: sum u .* (KM @ v)
    float D[4][4];
#pragma unroll
    for (int j = 0; j < 4; j++)
#pragma unroll
        for (int q = 0; q < 4; q++) D[j][q] = 0.0f;
    {
        const int lr = lane & 15, lh = lane >> 4;
        const uint32_t bhb = xB + lr * 80 + lh * 16;
#pragma unroll 4
        for (int kt = 0; kt < 16; kt++) {
            uint4 ah = Mh[(size_t)(w * 16 + kt) * 32 + lane];
            uint32_t bh[4][2], r[4];
            LDSM_X4T(r, bhb + kt * 1280);      bh[0][0]=r[0]; bh[0][1]=r[1]; bh[1][0]=r[2]; bh[1][1]=r[3];
            LDSM_X4T(r, bhb + kt * 1280 + 32); bh[2][0]=r[0]; bh[2][1]=r[1]; bh[3][0]=r[2]; bh[3][1]=r[3];
#pragma unroll
            for (int nt = 0; nt < 4; nt++)
                MMA_BF16(D[nt], ((uint32_t*)&ah), bh[nt]);
        }
    }
    float part = 0.0f;
#pragma unroll
    for (int nt = 0; nt < 4; nt++)
#pragma unroll
        for (int q = 0; q < 4; q++)
            part += u_r[nt*4+q] * D[nt][q];
#pragma unroll
    for (int o = 16; o > 0; o >>= 1) part += __shfl_xor_sync(0xffffffffu, part, o);
    float* RED = (float*)(smem + SK_RED);
    if (lane == 0) RED[w] = part;
    __syncthreads();
    if (tid == 0) {
        float t = 0.0f;
#pragma unroll
        for (int i = 0; i < 16; i++) t += RED[i];
        atomicAdd(loss, t);
    }
}

extern "C" void kernel_launch(void* const* d_in, const int* in_sizes, int n_in,
                              void* d_out, int out_size)
{
    const float* f    = (const float*)d_in[0];
    const float* head = (const float*)d_in[1];
    const float* W1   = (const float*)d_in[2];
    const float* b1   = (const float*)d_in[3];
    const float* W2   = (const float*)d_in[4];
    const float* b2   = (const float*)d_in[5];
    float* out    = (float*)d_out;
    float* scores = out;
    float* loss   = out + (out_size - 1);

    cudaFuncSetAttribute(sinkhorn_fused_kernel, cudaFuncAttributeMaxDynamicSharedMemorySize, SK_SMEM);

    init_kernel<<<1, 256>>>(loss);
    merged_kernel<<<MLP_GRID2, 256>>>(f, W1, b1, W2, b2, scores);
    kexp_kernel<<<512, 256>>>();
    sinkhorn_fused_kernel<<<128, 512, SK_SMEM>>>(scores, head, loss);
}